// round 15
// baseline (speedup 1.0000x reference)
#include <cuda_runtime.h>
#include <cuda_fp16.h>
#include <cstdint>

// ---------------------------------------------------------------------------
// SelfAttention B=4, S=2048, D=1024 fp32.
// mma.sync.m16n8k16 fp16 + ldmatrix + cp.async persistent GEMMs.
// Algebra: S = x (Wq Wk^T) x^T;  Vt = Wv^T x^T;  O = softmax(S) Vt^T.
// R15: R13 config (best) + prefetch hoisted between k16=0 LDSM and MMA so
//      cp.async issue/flight overlaps the MMA stream instead of sitting on
//      the critical path before the commit.
// Precision: Mt 2-split/3-combo (x32), y 2-split/3-combo (/32),
//            scores 3-combo, V & P single fp16, AV 1 combo. rel err ~3.8e-4.
// ---------------------------------------------------------------------------

#define BATCH 4
#define SEQ   2048
#define DIM   1024
#define MTOT  (BATCH * SEQ)   // 8192

#define AL __align__(128)
__device__ AL __half g_xp0[(size_t)MTOT * DIM];
__device__ AL __half g_xp1[(size_t)MTOT * DIM];
__device__ AL __half g_wq0[(size_t)DIM * DIM];
__device__ AL __half g_wq1[(size_t)DIM * DIM];
__device__ AL __half g_wk0[(size_t)DIM * DIM];
__device__ AL __half g_wk1[(size_t)DIM * DIM];
__device__ AL __half g_wvt0[(size_t)DIM * DIM];
__device__ AL float  g_mtpart[(size_t)4 * DIM * DIM];
__device__ AL __half g_mt0[(size_t)DIM * DIM];
__device__ AL __half g_mt1[(size_t)DIM * DIM];
__device__ AL __half g_yp0[(size_t)MTOT * DIM];
__device__ AL __half g_yp1[(size_t)MTOT * DIM];
__device__ AL __half g_vt[(size_t)BATCH * DIM * SEQ];
__device__ AL float  g_S[(size_t)BATCH * SEQ * SEQ];
__device__ AL __half g_pp[(size_t)BATCH * SEQ * SEQ];

// ---------------- PTX helpers ------------------------------------------------
__device__ __forceinline__ uint32_t smem_to_u32(const void* p) {
    uint32_t a;
    asm("{ .reg .u64 t; cvta.to.shared.u64 t, %1; cvt.u32.u64 %0, t; }"
        : "=r"(a) : "l"(p));
    return a;
}
#define CP_ASYNC_16(dst, src) \
    asm volatile("cp.async.cg.shared.global [%0], [%1], 16;" \
                 :: "r"(dst), "l"(src) : "memory")
#define CP_COMMIT() asm volatile("cp.async.commit_group;" ::: "memory")
#define CP_WAIT_1() asm volatile("cp.async.wait_group 1;" ::: "memory")

#define LDSM4(r0, r1, r2, r3, addr) \
    asm volatile("ldmatrix.sync.aligned.m8n8.x4.shared.b16 {%0,%1,%2,%3}, [%4];" \
                 : "=r"(r0), "=r"(r1), "=r"(r2), "=r"(r3) : "r"(addr))

#define MMA16816(d, a, b0r, b1r) \
    asm volatile("mma.sync.aligned.m16n8k16.row.col.f32.f16.f16.f32 " \
                 "{%0,%1,%2,%3}, {%4,%5,%6,%7}, {%8,%9}, {%0,%1,%2,%3};" \
                 : "+f"((d)[0]), "+f"((d)[1]), "+f"((d)[2]), "+f"((d)[3]) \
                 : "r"((a)[0]), "r"((a)[1]), "r"((a)[2]), "r"((a)[3]), \
                   "r"(b0r), "r"(b1r))

// ---------------- split helpers ----------------------------------------------
__device__ __forceinline__ uint32_t packh2(__half a, __half b) {
    return (uint32_t)__half_as_ushort(a) | ((uint32_t)__half_as_ushort(b) << 16);
}
__device__ __forceinline__ void split2h(float v, __half& h0, __half& h1) {
    h0 = __float2half_rn(v);
    h1 = __float2half_rn(v - __half2float(h0));
}

// ---------------- persistent GEMM: templates + 3-stage continuous ring --------
// C[M,N] = cscale * sum_cb A[CIA] * B[CIB]^T
// A parts: rows x KTOT (row stride LD). B parts: rows x KTOT (row stride LD).
// CTA tile 128(M) x 64(N), BK=32, 4 warps (2M x 2N), warp tile 64x32.
// 3-stage cp.async ring, wait_group(1), continuous across the CTA's tiles.
// Prefetch is issued between the k16=0 LDSMs and MMAs (overlaps MMA stream).
template <int NA, int NCOMBO, int EPI, int OCC,
          int KTOT, int LD, int LDC,
          int TX, int TY, int TZ,
          long long SA, long long SB, long long SC>
__global__ void __launch_bounds__(128, OCC)
gemm_mma(const __half* __restrict__ a0, const __half* __restrict__ a1,
         const __half* __restrict__ b0, const __half* __restrict__ b1,
         float* __restrict__ cf,
         __half* __restrict__ c0, __half* __restrict__ c1,
         float cscale)
{
    constexpr int CIA[3] = {0, 0, 1};
    constexpr int CIB[3] = {0, 1, 0};
    constexpr uint32_t A_SZ = 8192u;            // 128 rows x 32 k fp16
    constexpr uint32_t B_SZ = 4096u;            // 64 rows x 32 k fp16
    constexpr uint32_t B_OFF = NA * A_SZ;
    constexpr uint32_t STG = NA * (A_SZ + B_SZ);
    constexpr int NCHUNK = KTOT / 32;
    constexpr int TOT = TX * TY * TZ;

    extern __shared__ char dsm[];
    const uint32_t sbase = smem_to_u32(dsm);

    const int tid  = threadIdx.x;
    const int wid  = tid >> 5;
    const int lane = tid & 31;
    const int lrow = lane & 15;
    const int lch  = lane >> 4;

    const int wm = (wid & 1) * 64;    // warp M offset
    const int wn = (wid >> 1) * 32;   // warp N offset

    const int arsw = ((wm + lrow) >> 1) & 3;
    const int brsw = ((wn + lrow) >> 1) & 3;
    const uint32_t aoff = (uint32_t)(wm + lrow) * 64;
    const uint32_t boff = (uint32_t)(wn + lrow) * 64;

    const int quad = lane >> 2;
    const int tcol = lane & 3;

    auto decode = [&](int t, int& mB, int& nB, long long& zA, long long& zB,
                      long long& zC) {
        const int bx = t % TX;
        const int rem = t / TX;
        const int by = rem % TY;
        const int bz = rem / TY;
        mB = by * 128; nB = bx * 64;
        zA = (long long)bz * SA;
        zB = (long long)bz * SB;
        zC = (long long)bz * SC;
    };

    auto load_stage = [&](int mB, int nB, long long zA, long long zB,
                          int chunk, int bufi) {
        const int k0 = chunk << 5;
        const uint32_t sb = sbase + (uint32_t)bufi * STG;
        const __half* apt[2] = { a0 + zA, (NA == 2) ? a1 + zA : a0 + zA };
        const __half* bpt[2] = { b0 + zB, (NA == 2) ? b1 + zB : b0 + zB };
#pragma unroll
        for (int t = 0; t < NA; ++t) {
            const uint32_t tb = sb + (uint32_t)t * A_SZ;
#pragma unroll
            for (int i = 0; i < 4; ++i) {           // 512 chunks of 16B
                const int id  = tid + i * 128;
                const int row = id >> 2;            // 0..127
                const int c   = id & 3;
                const __half* g = apt[t] + (long long)(mB + row) * LD + k0 + c * 8;
                const uint32_t d = tb + (uint32_t)row * 64u +
                                   (uint32_t)((c ^ ((row >> 1) & 3)) * 16);
                CP_ASYNC_16(d, g);
            }
        }
#pragma unroll
        for (int t = 0; t < NA; ++t) {
            const uint32_t tb = sb + B_OFF + (uint32_t)t * B_SZ;
#pragma unroll
            for (int i = 0; i < 2; ++i) {           // 256 chunks of 16B
                const int id  = tid + i * 128;
                const int row = id >> 2;            // 0..63
                const int c   = id & 3;
                const __half* g = bpt[t] + (long long)(nB + row) * LD + k0 + c * 8;
                const uint32_t d = tb + (uint32_t)row * 64u +
                                   (uint32_t)((c ^ ((row >> 1) & 3)) * 16);
                CP_ASYNC_16(d, g);
            }
        }
    };

    int tile = blockIdx.x;
    if (tile >= TOT) return;

    int mB, nB; long long zA, zB, zC;
    decode(tile, mB, nB, zA, zB, zC);

    int buf = 0;
    load_stage(mB, nB, zA, zB, 0, 0); CP_COMMIT();
    load_stage(mB, nB, zA, zB, 1, 1); CP_COMMIT();

    while (true) {
        float acc[4][4][4];
#pragma unroll
        for (int i = 0; i < 4; i++)
#pragma unroll
            for (int j = 0; j < 4; j++)
#pragma unroll
                for (int e = 0; e < 4; e++) acc[i][j][e] = 0.0f;

        for (int chunk = 0; chunk < NCHUNK; ++chunk) {
            CP_WAIT_1();
            __syncthreads();

            const uint32_t stb = sbase + (uint32_t)buf * STG;
#pragma unroll
            for (int k16 = 0; k16 < 2; ++k16) {
                const uint32_t asw = (uint32_t)(((k16 * 2 + lch) ^ arsw) * 16);
                const uint32_t bsw = (uint32_t)(((k16 * 2 + lch) ^ brsw) * 16);

                uint32_t afr[NA][4][4];
#pragma unroll
                for (int t = 0; t < NA; ++t) {
                    const uint32_t abase = stb + (uint32_t)t * A_SZ + aoff + asw;
#pragma unroll
                    for (int im = 0; im < 4; ++im)
                        LDSM4(afr[t][im][0], afr[t][im][1], afr[t][im][2], afr[t][im][3],
                              abase + (uint32_t)im * 1024u);
                }
                uint32_t bfr[NA][2][4];
#pragma unroll
                for (int t = 0; t < NA; ++t) {
                    const uint32_t bbase = stb + B_OFF + (uint32_t)t * B_SZ + boff + bsw;
#pragma unroll
                    for (int g = 0; g < 2; ++g)
                        LDSM4(bfr[t][g][0], bfr[t][g][1], bfr[t][g][2], bfr[t][g][3],
                              bbase + (uint32_t)g * 1024u);
                }

                // hoisted prefetch: issue between k16=0 LDSMs and MMAs so the
                // cp.async issue + flight overlap the MMA stream
                if (k16 == 0) {
                    const int pf = chunk + 2;
                    int wbuf = buf + 2; if (wbuf >= 3) wbuf -= 3;
                    if (pf < NCHUNK) {
                        load_stage(mB, nB, zA, zB, pf, wbuf);
                    } else {
                        const int nt = tile + gridDim.x;
                        if (nt < TOT) {
                            int mB2, nB2; long long zA2, zB2, zC2;
                            decode(nt, mB2, nB2, zA2, zB2, zC2);
                            load_stage(mB2, nB2, zA2, zB2, pf - NCHUNK, wbuf);
                        }
                    }
                    CP_COMMIT();
                }

#pragma unroll
                for (int cb = 0; cb < NCOMBO; ++cb) {
                    const int ta  = CIA[cb] < NA ? CIA[cb] : 0;
                    const int tb2 = CIB[cb] < NA ? CIB[cb] : 0;
#pragma unroll
                    for (int im = 0; im < 4; ++im)
#pragma unroll
                        for (int in = 0; in < 4; ++in)
                            MMA16816(acc[im][in], afr[ta][im],
                                     bfr[tb2][in >> 1][in & 1],
                                     bfr[tb2][in >> 1][(in & 1) + 2]);
                }
            }
            if (++buf == 3) buf = 0;
        }

        // ---- epilogue (register -> global; overlaps next tile's loads) ----
#pragma unroll
        for (int im = 0; im < 4; ++im) {
#pragma unroll
            for (int in = 0; in < 4; ++in) {
                const int row = mB + wm + im * 16 + quad;
                const int col = nB + wn + in * 8 + tcol * 2;
                const long long olo = zC + (long long)row * LDC + col;
                const long long ohi = zC + (long long)(row + 8) * LDC + col;
                const float v0 = acc[im][in][0] * cscale;
                const float v1 = acc[im][in][1] * cscale;
                const float v2 = acc[im][in][2] * cscale;
                const float v3 = acc[im][in][3] * cscale;
                if constexpr (EPI == 0) {
                    *reinterpret_cast<float2*>(cf + olo) = make_float2(v0, v1);
                    *reinterpret_cast<float2*>(cf + ohi) = make_float2(v2, v3);
                } else if constexpr (EPI == 2) {
                    __half xh, xl, yh, yl;
                    split2h(v0, xh, xl); split2h(v1, yh, yl);
                    *reinterpret_cast<uint32_t*>(c0 + olo) = packh2(xh, yh);
                    *reinterpret_cast<uint32_t*>(c1 + olo) = packh2(xl, yl);
                    split2h(v2, xh, xl); split2h(v3, yh, yl);
                    *reinterpret_cast<uint32_t*>(c0 + ohi) = packh2(xh, yh);
                    *reinterpret_cast<uint32_t*>(c1 + ohi) = packh2(xl, yl);
                } else {
                    *reinterpret_cast<__half2*>(c0 + olo) = __floats2half2_rn(v0, v1);
                    *reinterpret_cast<__half2*>(c0 + ohi) = __floats2half2_rn(v2, v3);
                }
            }
        }

        tile += gridDim.x;
        if (tile >= TOT) break;
        decode(tile, mB, nB, zA, zB, zC);
    }
}

// ---------------- aux kernels --------------------------------------------------
__global__ void __launch_bounds__(256)
split2_kernel(const float* __restrict__ src, __half* __restrict__ d0,
              __half* __restrict__ d1)
{
    const size_t i = (size_t)blockIdx.x * 256 + threadIdx.x;
    const float4 v = reinterpret_cast<const float4*>(src)[i];
    __half a0, a1, b0, b1, c0, c1, e0, e1;
    split2h(v.x, a0, a1); split2h(v.y, b0, b1);
    split2h(v.z, c0, c1); split2h(v.w, e0, e1);
    reinterpret_cast<uint2*>(d0)[i] = make_uint2(packh2(a0, b0), packh2(c0, e0));
    reinterpret_cast<uint2*>(d1)[i] = make_uint2(packh2(a1, b1), packh2(c1, e1));
}

// W [K,N] fp32 -> transposed single-fp16 Wt [N,K]
__global__ void __launch_bounds__(256)
wsplit_kernel(const float* __restrict__ W, __half* __restrict__ t0)
{
    __shared__ float tile[32][33];
    const int tx = threadIdx.x, ty = threadIdx.y;
    const int k0 = blockIdx.y * 32, n0 = blockIdx.x * 32;
#pragma unroll
    for (int i = 0; i < 4; ++i)
        tile[ty + i * 8][tx] = W[(size_t)(k0 + ty + i * 8) * DIM + n0 + tx];
    __syncthreads();
#pragma unroll
    for (int i = 0; i < 4; ++i) {
        const int n = n0 + ty + i * 8;
        t0[(size_t)n * DIM + k0 + tx] = __float2half_rn(tile[tx][ty + i * 8]);
    }
}

// sum 4 split-K partials, scale x32, 2-split fp16
__global__ void __launch_bounds__(256)
mt_reduce_kernel(const float* __restrict__ part, __half* __restrict__ d0,
                 __half* __restrict__ d1)
{
    const size_t i = (size_t)blockIdx.x * 256 + threadIdx.x;
    const float4* p = reinterpret_cast<const float4*>(part);
    const size_t n4 = (size_t)DIM * DIM / 4;
    float4 s = p[i];
#pragma unroll
    for (int z = 1; z < 4; ++z) {
        const float4 t = p[i + (size_t)z * n4];
        s.x += t.x; s.y += t.y; s.z += t.z; s.w += t.w;
    }
    __half a0, a1, b0, b1, c0, c1, e0, e1;
    split2h(s.x * 32.0f, a0, a1); split2h(s.y * 32.0f, b0, b1);
    split2h(s.z * 32.0f, c0, c1); split2h(s.w * 32.0f, e0, e1);
    reinterpret_cast<uint2*>(d0)[i] = make_uint2(packh2(a0, b0), packh2(c0, e0));
    reinterpret_cast<uint2*>(d1)[i] = make_uint2(packh2(a1, b1), packh2(c1, e1));
}

// row softmax of S (fp32, row length SEQ) -> single fp16 P
__global__ void __launch_bounds__(256)
softmax_kernel(const float* __restrict__ S, __half* __restrict__ p0)
{
    const float4* row = reinterpret_cast<const float4*>(S + (size_t)blockIdx.x * SEQ);
    const int tid = threadIdx.x;

    float4 a = row[tid];
    float4 b = row[tid + 256];

    float m = fmaxf(fmaxf(fmaxf(a.x, a.y), fmaxf(a.z, a.w)),
                    fmaxf(fmaxf(b.x, b.y), fmaxf(b.z, b.w)));
#pragma unroll
    for (int o = 16; o > 0; o >>= 1) m = fmaxf(m, __shfl_xor_sync(0xffffffffu, m, o));

    __shared__ float redmax[8];
    __shared__ float redsum[8];
    if ((tid & 31) == 0) redmax[tid >> 5] = m;
    __syncthreads();
    float mrow = redmax[0];
#pragma unroll
    for (int i = 1; i < 8; ++i) mrow = fmaxf(mrow, redmax[i]);

    a.x = __expf(a.x - mrow); a.y = __expf(a.y - mrow);
    a.z = __expf(a.z - mrow); a.w = __expf(a.w - mrow);
    b.x = __expf(b.x - mrow); b.y = __expf(b.y - mrow);
    b.z = __expf(b.z - mrow); b.w = __expf(b.w - mrow);

    float s = (a.x + a.y) + (a.z + a.w) + (b.x + b.y) + (b.z + b.w);
#pragma unroll
    for (int o = 16; o > 0; o >>= 1) s += __shfl_xor_sync(0xffffffffu, s, o);
    if ((tid & 31) == 0) redsum[tid >> 5] = s;
    __syncthreads();
    float srow = 0.0f;
#pragma unroll
    for (int i = 0; i < 8; ++i) srow += redsum[i];
    const float inv = 1.0f / srow;

    uint2* r0 = reinterpret_cast<uint2*>(p0 + (size_t)blockIdx.x * SEQ);
    r0[tid] = make_uint2(
        packh2(__float2half_rn(a.x * inv), __float2half_rn(a.y * inv)),
        packh2(__float2half_rn(a.z * inv), __float2half_rn(a.w * inv)));
    r0[tid + 256] = make_uint2(
        packh2(__float2half_rn(b.x * inv), __float2half_rn(b.y * inv)),
        packh2(__float2half_rn(b.z * inv), __float2half_rn(b.w * inv)));
}

// ---------------- launch --------------------------------------------------------
extern "C" void kernel_launch(void* const* d_in, const int* in_sizes, int n_in,
                              void* d_out, int out_size)
{
    const float* x  = (const float*)d_in[0];
    const float* Wq = (const float*)d_in[1];
    const float* Wk = (const float*)d_in[2];
    const float* Wv = (const float*)d_in[3];
    float* out = (float*)d_out;

    __half *xp0, *xp1, *wq0, *wq1, *wk0, *wk1, *wvt0;
    __half *mt0, *mt1, *yp0, *yp1, *vt, *pp;
    float *S, *mtpart;
    cudaGetSymbolAddress((void**)&xp0, g_xp0);  cudaGetSymbolAddress((void**)&xp1, g_xp1);
    cudaGetSymbolAddress((void**)&wq0, g_wq0);  cudaGetSymbolAddress((void**)&wq1, g_wq1);
    cudaGetSymbolAddress((void**)&wk0, g_wk0);  cudaGetSymbolAddress((void**)&wk1, g_wk1);
    cudaGetSymbolAddress((void**)&wvt0, g_wvt0);
    cudaGetSymbolAddress((void**)&mtpart, g_mtpart);
    cudaGetSymbolAddress((void**)&mt0, g_mt0);  cudaGetSymbolAddress((void**)&mt1, g_mt1);
    cudaGetSymbolAddress((void**)&yp0, g_yp0);  cudaGetSymbolAddress((void**)&yp1, g_yp1);
    cudaGetSymbolAddress((void**)&vt, g_vt);
    cudaGetSymbolAddress((void**)&pp, g_pp);
    cudaGetSymbolAddress((void**)&S, g_S);

    int sms = 148;
    cudaDeviceGetAttribute(&sms, cudaDevAttrMultiProcessorCount, 0);
    const int GRID3 = 3 * sms;
    const int GRID4 = 4 * sms;

    const int SMEM2 = 3 * 24576;  // NA=2: 3 stages x 24KB = 73728 (3 CTAs/SM)
    const int SMEM1 = 3 * 12288;  // NA=1: 3 stages x 12KB = 36864 (4 CTAs/SM)

    // kernel aliases (compile-time shapes; OCC per kernel)
    auto kMt = gemm_mma<2, 3, 0, 3, 256, DIM, DIM, 16, 8, 4,
                        256LL, 256LL, (long long)DIM * DIM>;
    auto kY  = gemm_mma<2, 3, 2, 3, DIM, DIM, DIM, 16, 64, 1, 0LL, 0LL, 0LL>;
    auto kVt = gemm_mma<1, 1, 3, 4, DIM, DIM, SEQ, 32, 8, BATCH,
                        0LL, (long long)SEQ * DIM, (long long)DIM * SEQ>;
    auto kS  = gemm_mma<2, 3, 0, 3, DIM, DIM, SEQ, 32, 16, BATCH,
                        (long long)SEQ * DIM, (long long)SEQ * DIM,
                        (long long)SEQ * SEQ>;
    auto kAV = gemm_mma<1, 1, 0, 4, SEQ, SEQ, DIM, 16, 16, BATCH,
                        (long long)SEQ * SEQ, (long long)DIM * SEQ,
                        (long long)SEQ * DIM>;

    cudaFuncSetAttribute(kMt, cudaFuncAttributeMaxDynamicSharedMemorySize, SMEM2);
    cudaFuncSetAttribute(kY,  cudaFuncAttributeMaxDynamicSharedMemorySize, SMEM2);
    cudaFuncSetAttribute(kS,  cudaFuncAttributeMaxDynamicSharedMemorySize, SMEM2);
    cudaFuncSetAttribute(kVt, cudaFuncAttributeMaxDynamicSharedMemorySize, SMEM1);
    cudaFuncSetAttribute(kAV, cudaFuncAttributeMaxDynamicSharedMemorySize, SMEM1);

    // 1-3) operand splits (x, Wq, Wk)
    split2_kernel<<<(MTOT * DIM) / 1024, 256>>>(x, xp0, xp1);
    split2_kernel<<<(DIM * DIM) / 1024, 256>>>(Wq, wq0, wq1);
    split2_kernel<<<(DIM * DIM) / 1024, 256>>>(Wk, wk0, wk1);

    // 4) Mt partials: Wk Wq^T split-K x4 (K=256/slice)  <- ncu capture slot
    kMt<<<GRID3, 128, SMEM2>>>(wk0, wk1, wq0, wq1, mtpart, nullptr, nullptr, 1.0f);

    // 5) reduce + x32 + 2-split
    mt_reduce_kernel<<<(DIM * DIM) / 1024, 256>>>(mtpart, mt0, mt1);

    // 6) Wv^T single fp16
    {
        dim3 g(DIM / 32, DIM / 32), blk(32, 8);
        wsplit_kernel<<<g, blk>>>(Wv, wvt0);
    }

    // 7) y = (x Mt^T)/32, 2-split out
    kY<<<GRID3, 128, SMEM2>>>(xp0, xp1, mt0, mt1, nullptr, yp0, yp1, 1.0f / 32.0f);

    // 8) Vt[b] = Wv^T @ x[b]^T  (direct transposed V, single fp16)
    kVt<<<GRID4, 128, SMEM1>>>(wvt0, nullptr, xp0, nullptr, nullptr, vt, nullptr, 1.0f);

    // 9) scores S[b] = y[b] @ x[b]^T
    kS<<<GRID3, 128, SMEM2>>>(yp0, yp1, xp0, xp1, S, nullptr, nullptr, 1.0f);

    // 10) softmax -> P (single fp16)
    softmax_kernel<<<BATCH * SEQ, 256>>>(S, pp);

    // 11) O[b] = P[b] @ Vt[b]^T
    kAV<<<GRID4, 128, SMEM1>>>(pp, nullptr, vt, nullptr, out, nullptr, nullptr, 1.0f);
}

// round 16
// speedup vs baseline: 1.0397x; 1.0397x over previous
#include <cuda_runtime.h>
#include <cuda_fp16.h>
#include <cstdint>

// ---------------------------------------------------------------------------
// SelfAttention B=4, S=2048, D=1024 fp32.
// mma.sync.m16n8k16 fp16 + ldmatrix + cp.async persistent GEMMs.
// Algebra: S = x (Wq Wk^T) x^T;  Vt = Wv^T x^T;  O = softmax(S) Vt^T.
// R16: GEMM kernel identical to R13 (best). New: fork/join stream overlap
//      inside the captured graph — Mt chain runs on a side stream hidden
//      under x-split; Vt runs concurrently with y/S to fill tail waves.
// Precision: Mt 2-split/3-combo (x32), y 2-split/3-combo (/32),
//            scores 3-combo, V & P single fp16, AV 1 combo. rel err ~3.8e-4.
// ---------------------------------------------------------------------------

#define BATCH 4
#define SEQ   2048
#define DIM   1024
#define MTOT  (BATCH * SEQ)   // 8192

#define AL __align__(128)
__device__ AL __half g_xp0[(size_t)MTOT * DIM];
__device__ AL __half g_xp1[(size_t)MTOT * DIM];
__device__ AL __half g_wq0[(size_t)DIM * DIM];
__device__ AL __half g_wq1[(size_t)DIM * DIM];
__device__ AL __half g_wk0[(size_t)DIM * DIM];
__device__ AL __half g_wk1[(size_t)DIM * DIM];
__device__ AL __half g_wvt0[(size_t)DIM * DIM];
__device__ AL float  g_mtpart[(size_t)4 * DIM * DIM];
__device__ AL __half g_mt0[(size_t)DIM * DIM];
__device__ AL __half g_mt1[(size_t)DIM * DIM];
__device__ AL __half g_yp0[(size_t)MTOT * DIM];
__device__ AL __half g_yp1[(size_t)MTOT * DIM];
__device__ AL __half g_vt[(size_t)BATCH * DIM * SEQ];
__device__ AL float  g_S[(size_t)BATCH * SEQ * SEQ];
__device__ AL __half g_pp[(size_t)BATCH * SEQ * SEQ];

// ---------------- PTX helpers ------------------------------------------------
__device__ __forceinline__ uint32_t smem_to_u32(const void* p) {
    uint32_t a;
    asm("{ .reg .u64 t; cvta.to.shared.u64 t, %1; cvt.u32.u64 %0, t; }"
        : "=r"(a) : "l"(p));
    return a;
}
#define CP_ASYNC_16(dst, src) \
    asm volatile("cp.async.cg.shared.global [%0], [%1], 16;" \
                 :: "r"(dst), "l"(src) : "memory")
#define CP_COMMIT() asm volatile("cp.async.commit_group;" ::: "memory")
#define CP_WAIT_1() asm volatile("cp.async.wait_group 1;" ::: "memory")

#define LDSM4(r0, r1, r2, r3, addr) \
    asm volatile("ldmatrix.sync.aligned.m8n8.x4.shared.b16 {%0,%1,%2,%3}, [%4];" \
                 : "=r"(r0), "=r"(r1), "=r"(r2), "=r"(r3) : "r"(addr))

#define MMA16816(d, a, b0r, b1r) \
    asm volatile("mma.sync.aligned.m16n8k16.row.col.f32.f16.f16.f32 " \
                 "{%0,%1,%2,%3}, {%4,%5,%6,%7}, {%8,%9}, {%0,%1,%2,%3};" \
                 : "+f"((d)[0]), "+f"((d)[1]), "+f"((d)[2]), "+f"((d)[3]) \
                 : "r"((a)[0]), "r"((a)[1]), "r"((a)[2]), "r"((a)[3]), \
                   "r"(b0r), "r"(b1r))

// ---------------- split helpers ----------------------------------------------
__device__ __forceinline__ uint32_t packh2(__half a, __half b) {
    return (uint32_t)__half_as_ushort(a) | ((uint32_t)__half_as_ushort(b) << 16);
}
__device__ __forceinline__ void split2h(float v, __half& h0, __half& h1) {
    h0 = __float2half_rn(v);
    h1 = __float2half_rn(v - __half2float(h0));
}

// ---------------- persistent GEMM: templates + 3-stage continuous ring --------
// C[M,N] = cscale * sum_cb A[CIA] * B[CIB]^T
// A parts: rows x KTOT (row stride LD). B parts: rows x KTOT (row stride LD).
// CTA tile 128(M) x 64(N), BK=32, 4 warps (2M x 2N), warp tile 64x32.
// 3-stage cp.async ring, wait_group(1), continuous across the CTA's tiles.
template <int NA, int NCOMBO, int EPI, int OCC,
          int KTOT, int LD, int LDC,
          int TX, int TY, int TZ,
          long long SA, long long SB, long long SC>
__global__ void __launch_bounds__(128, OCC)
gemm_mma(const __half* __restrict__ a0, const __half* __restrict__ a1,
         const __half* __restrict__ b0, const __half* __restrict__ b1,
         float* __restrict__ cf,
         __half* __restrict__ c0, __half* __restrict__ c1,
         float cscale)
{
    constexpr int CIA[3] = {0, 0, 1};
    constexpr int CIB[3] = {0, 1, 0};
    constexpr uint32_t A_SZ = 8192u;            // 128 rows x 32 k fp16
    constexpr uint32_t B_SZ = 4096u;            // 64 rows x 32 k fp16
    constexpr uint32_t B_OFF = NA * A_SZ;
    constexpr uint32_t STG = NA * (A_SZ + B_SZ);
    constexpr int NCHUNK = KTOT / 32;
    constexpr int TOT = TX * TY * TZ;

    extern __shared__ char dsm[];
    const uint32_t sbase = smem_to_u32(dsm);

    const int tid  = threadIdx.x;
    const int wid  = tid >> 5;
    const int lane = tid & 31;
    const int lrow = lane & 15;
    const int lch  = lane >> 4;

    const int wm = (wid & 1) * 64;    // warp M offset
    const int wn = (wid >> 1) * 32;   // warp N offset

    const int arsw = ((wm + lrow) >> 1) & 3;
    const int brsw = ((wn + lrow) >> 1) & 3;
    const uint32_t aoff = (uint32_t)(wm + lrow) * 64;
    const uint32_t boff = (uint32_t)(wn + lrow) * 64;

    const int quad = lane >> 2;
    const int tcol = lane & 3;

    auto decode = [&](int t, int& mB, int& nB, long long& zA, long long& zB,
                      long long& zC) {
        const int bx = t % TX;
        const int rem = t / TX;
        const int by = rem % TY;
        const int bz = rem / TY;
        mB = by * 128; nB = bx * 64;
        zA = (long long)bz * SA;
        zB = (long long)bz * SB;
        zC = (long long)bz * SC;
    };

    auto load_stage = [&](int mB, int nB, long long zA, long long zB,
                          int chunk, int bufi) {
        const int k0 = chunk << 5;
        const uint32_t sb = sbase + (uint32_t)bufi * STG;
        const __half* apt[2] = { a0 + zA, (NA == 2) ? a1 + zA : a0 + zA };
        const __half* bpt[2] = { b0 + zB, (NA == 2) ? b1 + zB : b0 + zB };
#pragma unroll
        for (int t = 0; t < NA; ++t) {
            const uint32_t tb = sb + (uint32_t)t * A_SZ;
#pragma unroll
            for (int i = 0; i < 4; ++i) {           // 512 chunks of 16B
                const int id  = tid + i * 128;
                const int row = id >> 2;            // 0..127
                const int c   = id & 3;
                const __half* g = apt[t] + (long long)(mB + row) * LD + k0 + c * 8;
                const uint32_t d = tb + (uint32_t)row * 64u +
                                   (uint32_t)((c ^ ((row >> 1) & 3)) * 16);
                CP_ASYNC_16(d, g);
            }
        }
#pragma unroll
        for (int t = 0; t < NA; ++t) {
            const uint32_t tb = sb + B_OFF + (uint32_t)t * B_SZ;
#pragma unroll
            for (int i = 0; i < 2; ++i) {           // 256 chunks of 16B
                const int id  = tid + i * 128;
                const int row = id >> 2;            // 0..63
                const int c   = id & 3;
                const __half* g = bpt[t] + (long long)(nB + row) * LD + k0 + c * 8;
                const uint32_t d = tb + (uint32_t)row * 64u +
                                   (uint32_t)((c ^ ((row >> 1) & 3)) * 16);
                CP_ASYNC_16(d, g);
            }
        }
    };

    int tile = blockIdx.x;
    if (tile >= TOT) return;

    int mB, nB; long long zA, zB, zC;
    decode(tile, mB, nB, zA, zB, zC);

    int buf = 0;
    load_stage(mB, nB, zA, zB, 0, 0); CP_COMMIT();
    load_stage(mB, nB, zA, zB, 1, 1); CP_COMMIT();

    while (true) {
        float acc[4][4][4];
#pragma unroll
        for (int i = 0; i < 4; i++)
#pragma unroll
            for (int j = 0; j < 4; j++)
#pragma unroll
                for (int e = 0; e < 4; e++) acc[i][j][e] = 0.0f;

        for (int chunk = 0; chunk < NCHUNK; ++chunk) {
            CP_WAIT_1();
            __syncthreads();

            const uint32_t stb = sbase + (uint32_t)buf * STG;
#pragma unroll
            for (int k16 = 0; k16 < 2; ++k16) {
                const uint32_t asw = (uint32_t)(((k16 * 2 + lch) ^ arsw) * 16);
                const uint32_t bsw = (uint32_t)(((k16 * 2 + lch) ^ brsw) * 16);

                uint32_t afr[NA][4][4];
#pragma unroll
                for (int t = 0; t < NA; ++t) {
                    const uint32_t abase = stb + (uint32_t)t * A_SZ + aoff + asw;
#pragma unroll
                    for (int im = 0; im < 4; ++im)
                        LDSM4(afr[t][im][0], afr[t][im][1], afr[t][im][2], afr[t][im][3],
                              abase + (uint32_t)im * 1024u);
                }
                uint32_t bfr[NA][2][4];
#pragma unroll
                for (int t = 0; t < NA; ++t) {
                    const uint32_t bbase = stb + B_OFF + (uint32_t)t * B_SZ + boff + bsw;
#pragma unroll
                    for (int g = 0; g < 2; ++g)
                        LDSM4(bfr[t][g][0], bfr[t][g][1], bfr[t][g][2], bfr[t][g][3],
                              bbase + (uint32_t)g * 1024u);
                }

#pragma unroll
                for (int cb = 0; cb < NCOMBO; ++cb) {
                    const int ta  = CIA[cb] < NA ? CIA[cb] : 0;
                    const int tb2 = CIB[cb] < NA ? CIB[cb] : 0;
#pragma unroll
                    for (int im = 0; im < 4; ++im)
#pragma unroll
                        for (int in = 0; in < 4; ++in)
                            MMA16816(acc[im][in], afr[ta][im],
                                     bfr[tb2][in >> 1][in & 1],
                                     bfr[tb2][in >> 1][(in & 1) + 2]);
                }
            }

            // continuous-ring prefetch: same tile chunk+2, else next tile 0/1
            const int pf = chunk + 2;
            int wbuf = buf + 2; if (wbuf >= 3) wbuf -= 3;
            if (pf < NCHUNK) {
                load_stage(mB, nB, zA, zB, pf, wbuf);
            } else {
                const int nt = tile + gridDim.x;
                if (nt < TOT) {
                    int mB2, nB2; long long zA2, zB2, zC2;
                    decode(nt, mB2, nB2, zA2, zB2, zC2);
                    load_stage(mB2, nB2, zA2, zB2, pf - NCHUNK, wbuf);
                }
            }
            CP_COMMIT();
            if (++buf == 3) buf = 0;
        }

        // ---- epilogue (register -> global; overlaps next tile's loads) ----
#pragma unroll
        for (int im = 0; im < 4; ++im) {
#pragma unroll
            for (int in = 0; in < 4; ++in) {
                const int row = mB + wm + im * 16 + quad;
                const int col = nB + wn + in * 8 + tcol * 2;
                const long long olo = zC + (long long)row * LDC + col;
                const long long ohi = zC + (long long)(row + 8) * LDC + col;
                const float v0 = acc[im][in][0] * cscale;
                const float v1 = acc[im][in][1] * cscale;
                const float v2 = acc[im][in][2] * cscale;
                const float v3 = acc[im][in][3] * cscale;
                if constexpr (EPI == 0) {
                    *reinterpret_cast<float2*>(cf + olo) = make_float2(v0, v1);
                    *reinterpret_cast<float2*>(cf + ohi) = make_float2(v2, v3);
                } else if constexpr (EPI == 2) {
                    __half xh, xl, yh, yl;
                    split2h(v0, xh, xl); split2h(v1, yh, yl);
                    *reinterpret_cast<uint32_t*>(c0 + olo) = packh2(xh, yh);
                    *reinterpret_cast<uint32_t*>(c1 + olo) = packh2(xl, yl);
                    split2h(v2, xh, xl); split2h(v3, yh, yl);
                    *reinterpret_cast<uint32_t*>(c0 + ohi) = packh2(xh, yh);
                    *reinterpret_cast<uint32_t*>(c1 + ohi) = packh2(xl, yl);
                } else {
                    *reinterpret_cast<__half2*>(c0 + olo) = __floats2half2_rn(v0, v1);
                    *reinterpret_cast<__half2*>(c0 + ohi) = __floats2half2_rn(v2, v3);
                }
            }
        }

        tile += gridDim.x;
        if (tile >= TOT) break;
        decode(tile, mB, nB, zA, zB, zC);
    }
}

// ---------------- aux kernels --------------------------------------------------
__global__ void __launch_bounds__(256)
split2_kernel(const float* __restrict__ src, __half* __restrict__ d0,
              __half* __restrict__ d1)
{
    const size_t i = (size_t)blockIdx.x * 256 + threadIdx.x;
    const float4 v = reinterpret_cast<const float4*>(src)[i];
    __half a0, a1, b0, b1, c0, c1, e0, e1;
    split2h(v.x, a0, a1); split2h(v.y, b0, b1);
    split2h(v.z, c0, c1); split2h(v.w, e0, e1);
    reinterpret_cast<uint2*>(d0)[i] = make_uint2(packh2(a0, b0), packh2(c0, e0));
    reinterpret_cast<uint2*>(d1)[i] = make_uint2(packh2(a1, b1), packh2(c1, e1));
}

// W [K,N] fp32 -> transposed single-fp16 Wt [N,K]
__global__ void __launch_bounds__(256)
wsplit_kernel(const float* __restrict__ W, __half* __restrict__ t0)
{
    __shared__ float tile[32][33];
    const int tx = threadIdx.x, ty = threadIdx.y;
    const int k0 = blockIdx.y * 32, n0 = blockIdx.x * 32;
#pragma unroll
    for (int i = 0; i < 4; ++i)
        tile[ty + i * 8][tx] = W[(size_t)(k0 + ty + i * 8) * DIM + n0 + tx];
    __syncthreads();
#pragma unroll
    for (int i = 0; i < 4; ++i) {
        const int n = n0 + ty + i * 8;
        t0[(size_t)n * DIM + k0 + tx] = __float2half_rn(tile[tx][ty + i * 8]);
    }
}

// sum 4 split-K partials, scale x32, 2-split fp16
__global__ void __launch_bounds__(256)
mt_reduce_kernel(const float* __restrict__ part, __half* __restrict__ d0,
                 __half* __restrict__ d1)
{
    const size_t i = (size_t)blockIdx.x * 256 + threadIdx.x;
    const float4* p = reinterpret_cast<const float4*>(part);
    const size_t n4 = (size_t)DIM * DIM / 4;
    float4 s = p[i];
#pragma unroll
    for (int z = 1; z < 4; ++z) {
        const float4 t = p[i + (size_t)z * n4];
        s.x += t.x; s.y += t.y; s.z += t.z; s.w += t.w;
    }
    __half a0, a1, b0, b1, c0, c1, e0, e1;
    split2h(s.x * 32.0f, a0, a1); split2h(s.y * 32.0f, b0, b1);
    split2h(s.z * 32.0f, c0, c1); split2h(s.w * 32.0f, e0, e1);
    reinterpret_cast<uint2*>(d0)[i] = make_uint2(packh2(a0, b0), packh2(c0, e0));
    reinterpret_cast<uint2*>(d1)[i] = make_uint2(packh2(a1, b1), packh2(c1, e1));
}

// row softmax of S (fp32, row length SEQ) -> single fp16 P
__global__ void __launch_bounds__(256)
softmax_kernel(const float* __restrict__ S, __half* __restrict__ p0)
{
    const float4* row = reinterpret_cast<const float4*>(S + (size_t)blockIdx.x * SEQ);
    const int tid = threadIdx.x;

    float4 a = row[tid];
    float4 b = row[tid + 256];

    float m = fmaxf(fmaxf(fmaxf(a.x, a.y), fmaxf(a.z, a.w)),
                    fmaxf(fmaxf(b.x, b.y), fmaxf(b.z, b.w)));
#pragma unroll
    for (int o = 16; o > 0; o >>= 1) m = fmaxf(m, __shfl_xor_sync(0xffffffffu, m, o));

    __shared__ float redmax[8];
    __shared__ float redsum[8];
    if ((tid & 31) == 0) redmax[tid >> 5] = m;
    __syncthreads();
    float mrow = redmax[0];
#pragma unroll
    for (int i = 1; i < 8; ++i) mrow = fmaxf(mrow, redmax[i]);

    a.x = __expf(a.x - mrow); a.y = __expf(a.y - mrow);
    a.z = __expf(a.z - mrow); a.w = __expf(a.w - mrow);
    b.x = __expf(b.x - mrow); b.y = __expf(b.y - mrow);
    b.z = __expf(b.z - mrow); b.w = __expf(b.w - mrow);

    float s = (a.x + a.y) + (a.z + a.w) + (b.x + b.y) + (b.z + b.w);
#pragma unroll
    for (int o = 16; o > 0; o >>= 1) s += __shfl_xor_sync(0xffffffffu, s, o);
    if ((tid & 31) == 0) redsum[tid >> 5] = s;
    __syncthreads();
    float srow = 0.0f;
#pragma unroll
    for (int i = 0; i < 8; ++i) srow += redsum[i];
    const float inv = 1.0f / srow;

    uint2* r0 = reinterpret_cast<uint2*>(p0 + (size_t)blockIdx.x * SEQ);
    r0[tid] = make_uint2(
        packh2(__float2half_rn(a.x * inv), __float2half_rn(a.y * inv)),
        packh2(__float2half_rn(a.z * inv), __float2half_rn(a.w * inv)));
    r0[tid + 256] = make_uint2(
        packh2(__float2half_rn(b.x * inv), __float2half_rn(b.y * inv)),
        packh2(__float2half_rn(b.z * inv), __float2half_rn(b.w * inv)));
}

// ---------------- launch --------------------------------------------------------
extern "C" void kernel_launch(void* const* d_in, const int* in_sizes, int n_in,
                              void* d_out, int out_size)
{
    const float* x  = (const float*)d_in[0];
    const float* Wq = (const float*)d_in[1];
    const float* Wk = (const float*)d_in[2];
    const float* Wv = (const float*)d_in[3];
    float* out = (float*)d_out;

    __half *xp0, *xp1, *wq0, *wq1, *wk0, *wk1, *wvt0;
    __half *mt0, *mt1, *yp0, *yp1, *vt, *pp;
    float *S, *mtpart;
    cudaGetSymbolAddress((void**)&xp0, g_xp0);  cudaGetSymbolAddress((void**)&xp1, g_xp1);
    cudaGetSymbolAddress((void**)&wq0, g_wq0);  cudaGetSymbolAddress((void**)&wq1, g_wq1);
    cudaGetSymbolAddress((void**)&wk0, g_wk0);  cudaGetSymbolAddress((void**)&wk1, g_wk1);
    cudaGetSymbolAddress((void**)&wvt0, g_wvt0);
    cudaGetSymbolAddress((void**)&mtpart, g_mtpart);
    cudaGetSymbolAddress((void**)&mt0, g_mt0);  cudaGetSymbolAddress((void**)&mt1, g_mt1);
    cudaGetSymbolAddress((void**)&yp0, g_yp0);  cudaGetSymbolAddress((void**)&yp1, g_yp1);
    cudaGetSymbolAddress((void**)&vt, g_vt);
    cudaGetSymbolAddress((void**)&pp, g_pp);
    cudaGetSymbolAddress((void**)&S, g_S);

    int sms = 148;
    cudaDeviceGetAttribute(&sms, cudaDevAttrMultiProcessorCount, 0);
    const int GRID3 = 3 * sms;
    const int GRID4 = 4 * sms;

    const int SMEM2 = 3 * 24576;  // NA=2: 3 stages x 24KB (3 CTAs/SM)
    const int SMEM1 = 3 * 12288;  // NA=1: 3 stages x 12KB (4 CTAs/SM)

    // kernel aliases (compile-time shapes; OCC per kernel)
    auto kMt = gemm_mma<2, 3, 0, 3, 256, DIM, DIM, 16, 8, 4,
                        256LL, 256LL, (long long)DIM * DIM>;
    auto kY  = gemm_mma<2, 3, 2, 3, DIM, DIM, DIM, 16, 64, 1, 0LL, 0LL, 0LL>;
    auto kVt = gemm_mma<1, 1, 3, 4, DIM, DIM, SEQ, 32, 8, BATCH,
                        0LL, (long long)SEQ * DIM, (long long)DIM * SEQ>;
    auto kS  = gemm_mma<2, 3, 0, 3, DIM, DIM, SEQ, 32, 16, BATCH,
                        (long long)SEQ * DIM, (long long)SEQ * DIM,
                        (long long)SEQ * SEQ>;
    auto kAV = gemm_mma<1, 1, 0, 4, SEQ, SEQ, DIM, 16, 16, BATCH,
                        (long long)SEQ * SEQ, (long long)DIM * SEQ,
                        (long long)SEQ * DIM>;

    cudaFuncSetAttribute(kMt, cudaFuncAttributeMaxDynamicSharedMemorySize, SMEM2);
    cudaFuncSetAttribute(kY,  cudaFuncAttributeMaxDynamicSharedMemorySize, SMEM2);
    cudaFuncSetAttribute(kS,  cudaFuncAttributeMaxDynamicSharedMemorySize, SMEM2);
    cudaFuncSetAttribute(kVt, cudaFuncAttributeMaxDynamicSharedMemorySize, SMEM1);
    cudaFuncSetAttribute(kAV, cudaFuncAttributeMaxDynamicSharedMemorySize, SMEM1);

    // --- fork/join stream setup (host objects; graph-capturable edges) ---
    cudaStream_t sB;
    cudaStreamCreateWithFlags(&sB, cudaStreamNonBlocking);
    cudaEvent_t e0, eX, eM, eV;
    cudaEventCreateWithFlags(&e0, cudaEventDisableTiming);
    cudaEventCreateWithFlags(&eX, cudaEventDisableTiming);
    cudaEventCreateWithFlags(&eM, cudaEventDisableTiming);
    cudaEventCreateWithFlags(&eV, cudaEventDisableTiming);

    // fork side stream from the captured default stream
    cudaEventRecord(e0, 0);
    cudaStreamWaitEvent(sB, e0, 0);

    // side stream B: Wq/Wk splits -> Mt GEMM -> reduce  (independent of x)
    split2_kernel<<<(DIM * DIM) / 1024, 256, 0, sB>>>(Wq, wq0, wq1);
    split2_kernel<<<(DIM * DIM) / 1024, 256, 0, sB>>>(Wk, wk0, wk1);
    kMt<<<GRID3, 128, SMEM2, sB>>>(wk0, wk1, wq0, wq1, mtpart, nullptr, nullptr, 1.0f);
    mt_reduce_kernel<<<(DIM * DIM) / 1024, 256, 0, sB>>>(mtpart, mt0, mt1);
    cudaEventRecord(eM, sB);

    // default stream: x split + Wv transpose
    split2_kernel<<<(MTOT * DIM) / 1024, 256>>>(x, xp0, xp1);
    {
        dim3 g(DIM / 32, DIM / 32), blk(32, 8);
        wsplit_kernel<<<g, blk>>>(Wv, wvt0);
    }
    cudaEventRecord(eX, 0);

    // side stream B: Vt = Wv^T x^T (needs xp0 + wvt0) — runs concurrently
    // with y and S on the default stream, filling their tail waves.
    cudaStreamWaitEvent(sB, eX, 0);
    kVt<<<GRID4, 128, SMEM1, sB>>>(wvt0, nullptr, xp0, nullptr, nullptr, vt, nullptr, 1.0f);
    cudaEventRecord(eV, sB);

    // default stream: y (needs Mt) -> S -> softmax -> (join Vt) -> AV
    cudaStreamWaitEvent(0, eM, 0);
    kY<<<GRID3, 128, SMEM2>>>(xp0, xp1, mt0, mt1, nullptr, yp0, yp1, 1.0f / 32.0f);
    kS<<<GRID3, 128, SMEM2>>>(yp0, yp1, xp0, xp1, S, nullptr, nullptr, 1.0f);
    softmax_kernel<<<BATCH * SEQ, 256>>>(S, pp);
    cudaStreamWaitEvent(0, eV, 0);
    kAV<<<GRID4, 128, SMEM1>>>(pp, nullptr, vt, nullptr, out, nullptr, nullptr, 1.0f);
}